// round 14
// baseline (speedup 1.0000x reference)
#include <cuda_runtime.h>
#include <math.h>
#include <stdint.h>

// Problem constants (fixed by the reference)
#define NW      65536
#define TPB     256
#define PPB     256                // walker pairs per block (1 packed pair/thread)
#define NBLK    128                // 32768 pairs / 256; divides 2^32
#define TOTALS  512
#define WARM    128
#define NSTEPS  384
#define CH      16                 // steps per chunk
#define HB      8                  // steps per precompute half-block
#define NCH     (TOTALS / CH)      // 32
#define WARM_CH (WARM / CH)        // 8
#define ROWB    ((size_t)NW * 4)   // gmem bytes per step-row
// smem ring (ull units): stage = [N: CH*PPB][U: CH*PPB]
#define UOFF    (CH * PPB)         // 4096 ull
#define STG     (2 * CH * PPB)     // 8192 ull = 64 KB
#define SMEM_BYTES (3 * STG * 8)   // 192 KB

typedef unsigned long long ull;

// 8 slots (4 moments + 4 zero pads) keeps the validated reduction shape
__device__ float        g_part[8][NBLK];
__device__ unsigned int g_ctr = 0;

// ---------- f32x2 packed helpers ----------
__device__ __forceinline__ ull PKF(float a, float b) {
    ull v; asm("mov.b64 %0, {%1, %2};" : "=l"(v)
               : "r"(__float_as_uint(a)), "r"(__float_as_uint(b)));
    return v;
}
__device__ __forceinline__ ull PKU(unsigned a, unsigned b) {
    ull v; asm("mov.b64 %0, {%1, %2};" : "=l"(v) : "r"(a), "r"(b));
    return v;
}
__device__ __forceinline__ float LO(ull v) { return __uint_as_float((unsigned)v); }
__device__ __forceinline__ float HI(ull v) { return __uint_as_float((unsigned)(v >> 32)); }
__device__ __forceinline__ ull FMA2(ull a, ull b, ull c) {
    ull d; asm("fma.rn.f32x2 %0, %1, %2, %3;" : "=l"(d) : "l"(a), "l"(b), "l"(c));
    return d;
}
__device__ __forceinline__ ull MUL2(ull a, ull b) {
    ull d; asm("mul.rn.f32x2 %0, %1, %2;" : "=l"(d) : "l"(a), "l"(b));
    return d;
}
__device__ __forceinline__ ull ADD2(ull a, ull b) {
    ull d; asm("add.rn.f32x2 %0, %1, %2;" : "=l"(d) : "l"(a), "l"(b));
    return d;
}
__device__ __forceinline__ ull SPL(float a) { return PKF(a, a); }

// 8-byte cp.async: thread copies ONLY its own (n,u) words -> no cross-thread deps
__device__ __forceinline__ void cp8(uint32_t dst, const void* src) {
    asm volatile("cp.async.ca.shared.global [%0], [%1], 8;" :: "r"(dst), "l"(src));
}

__global__ void __launch_bounds__(TPB, 1) vmc_kernel(
    const float* __restrict__ theta,
    const float* __restrict__ r0,
    const float* __restrict__ sdevp,
    const float* __restrict__ noise,
    const float* __restrict__ unif,
    float* __restrict__ out, int out_size)
{
    extern __shared__ ull ring[];
    float* shred = (float*)ring;             // aliased reduction scratch

    const int tid = threadIdx.x;
    const int blk = blockIdx.x;
    const int w   = blk * PPB + tid;         // walker-pair index

    const float th0 = theta[0];
    const float th1 = theta[1];
    const float th2 = theta[2];
    const float sdev = sdevp[0];

    const float kk = __fmul_rn(-2.0f, th1);   // reference rounding (validated)
    const float gf = 2.0f * th1;

    const ull sd2  = SPL(sdev);
    const ull kk2  = SPL(kk);
    const ull mkk2 = SPL(-kk);

    // cheap comparison-grade ln (validated R11-R13): m in [2/3,4/3), f=m-1
    const ull cm1 = SPL(-1.0f);
    const ull cP5 = SPL(-0.16666667f), cP4 = SPL(0.2f);
    const ull cP3 = SPL(-0.25f),       cP2 = SPL(0.33333334f);
    const ull cP1 = SPL(-0.5f),        cP0 = SPL(1.0f);
    const ull cE  = SPL(8.2629582e-8f);      // 2^-23 * ln 2

    // Energy poly coefficients (fp64 fold once); applied only in epilogue
    const double dth0 = (double)th0, dth1 = (double)th1;
    const double dg = 2.0 * dth1, g2d = dg * dg;
    const double dC1 = -2.0 * exp(-dth1) * cos(dth0);
    const double dC2 =  2.0 * exp(-dth1) * sin(dth0);
    const float A0f = (float)dC1;
    const float A1f = (float)(dC1 * g2d / 2.0);
    const float A2f = (float)(dC1 * g2d / 2.0 * g2d / 12.0);
    const float B0f = (float)(dC2 * dg);
    const float B1f = (float)(dC2 * dg * g2d / 6.0);

    // ---- state: one packed pair per thread ----
    const float2 rr = ((const float2*)r0)[w];
    ull xs  = PKF(__fsub_rn(rr.x, th2), __fsub_rn(rr.y, th2));
    ull xs2 = MUL2(xs, xs);
    ull nkx = MUL2(mkk2, xs2);

    // ---- cp.async geometry: per-thread-private 8B granules ----
    const uint32_t base = (uint32_t)__cvta_generic_to_shared(ring);
    const char* gN = (const char*)noise + (size_t)w * 8;
    const char* gU = (const char*)unif  + (size_t)w * 8;
    const uint32_t tOff = (uint32_t)tid * 8;

    // chunk = 16 rows; thread copies its own ull per row per array (32 cp8)
#define ISSUE_CHUNK(s0, stg) do {                                            \
        const char* _n = gN + (size_t)(s0) * ROWB;                           \
        const char* _u = gU + (size_t)(s0) * ROWB;                           \
        uint32_t _sb = base + (uint32_t)(stg) * (STG * 8) + tOff;            \
        _Pragma("unroll")                                                    \
        for (int _r = 0; _r < CH; _r++) {                                    \
            uint32_t _d = (uint32_t)(_r * 2048);                             \
            cp8(_sb + _d,            _n + (size_t)_r * ROWB);                \
            cp8(_sb + UOFF * 8 + _d, _u + (size_t)_r * ROWB);                \
        }                                                                    \
        asm volatile("cp.async.commit_group;" ::: "memory");                 \
    } while (0)

    // packed cheap natural log (off-chain): 8 fma-pipe ops
#define NLOG(u, lgu) do {                                                    \
        unsigned iu0 = (unsigned)(u);                                        \
        unsigned iu1 = (unsigned)((u) >> 32);                                \
        int e0 = (int)((iu0 - 0x3f2aaaabu) & 0xff800000u);                   \
        int e1 = (int)((iu1 - 0x3f2aaaabu) & 0xff800000u);                   \
        float mm0 = __int_as_float((int)iu0 - e0);                           \
        float mm1 = __int_as_float((int)iu1 - e1);                           \
        ull f_ = ADD2(PKF(mm0, mm1), cm1);                                   \
        ull p_ = FMA2(cP5, f_, cP4);                                         \
        p_ = FMA2(p_, f_, cP3);                                              \
        p_ = FMA2(p_, f_, cP2);                                              \
        p_ = FMA2(p_, f_, cP1);                                              \
        p_ = FMA2(p_, f_, cP0);                                              \
        ull ln_ = MUL2(f_, p_);                                              \
        (lgu) = FMA2(PKF((float)e0, (float)e1), cE, ln_);                    \
    } while (0)

    // short recurrence (validated R13); bit-identical trajectory
#define REC(nn, lg) do {                                                     \
        ull xp  = FMA2(sd2, (nn), xs);                                       \
        ull xp2 = MUL2(xp, xp);                                              \
        ull lr  = FMA2(kk2, xp2, nkx);                                       \
        bool aLo = (LO(lg) < LO(lr));                                        \
        bool aHi = (HI(lg) < HI(lr));                                        \
        unsigned xs_lo = aLo ? (unsigned)xp         : (unsigned)xs;          \
        unsigned xs_hi = aHi ? (unsigned)(xp  >> 32) : (unsigned)(xs  >> 32); \
        xs  = PKU(xs_lo, xs_hi);                                             \
        xs2 = MUL2(xs, xs);                                                  \
        nkx = MUL2(mkk2, xs2);                                               \
    } while (0)

    // moment accumulation fused: M1=Sxs M2=St M3=Sxs3 M4=St2 (4 ops)
#define MEAS() do {                                                          \
        ull t = xs2;                                                         \
        M1 = ADD2(M1, xs);                                                   \
        M2 = ADD2(M2, t);                                                    \
        M3 = FMA2(xs, t, M3);                                                \
        M4 = FMA2(t,  t, M4);                                                \
    } while (0)

    ull M1 = 0, M2 = 0, M3 = 0, M4 = 0;

    // prologue: 2 chunks in flight (3-stage ring)
    ISSUE_CHUNK(0 * CH, 0);
    ISSUE_CHUNK(1 * CH, 1);

    int cur = 0;                    // slot of chunk c
    for (int c = 0; c < NCH; c++) {
        // Issue chunk c+2 FIRST (overlaps the wait). Slot (c+2)%3 held chunk
        // c-1, whose words THIS thread alone wrote and has fully consumed
        // (in-order issue: consumers preceded this point) -> no barrier needed.
        const int iss = (cur == 0) ? 2 : cur - 1;   // (c+2) % 3
        if (c + 2 < NCH) {
            ISSUE_CHUNK((c + 2) * CH, iss);
        } else {
            asm volatile("cp.async.commit_group;" ::: "memory");
        }
        // Outstanding groups: c, c+1, c+2 -> wait until chunk c done (<=2 younger)
        asm volatile("cp.async.wait_group 2;" ::: "memory");

        const ull* st = ring + (size_t)cur * STG;
        const bool meas = (c >= WARM_CH);

#pragma unroll
        for (int h = 0; h < CH / HB; h++) {
            ull nn[HB], lg[HB];
#pragma unroll
            for (int j = 0; j < HB; j++) {
                const int row = h * HB + j;
                nn[j] = st[row * PPB + tid];
                ull u = st[UOFF + row * PPB + tid];
                NLOG(u, lg[j]);
            }
            if (!meas) {
#pragma unroll
                for (int j = 0; j < HB; j++) { REC(nn[j], lg[j]); }
            } else {
#pragma unroll
                for (int j = 0; j < HB; j++) { REC(nn[j], lg[j]); MEAS(); }
            }
        }
        cur = (cur == 2) ? 0 : cur + 1;
    }

    // drain all async copies before aliasing the ring as reduction scratch
    asm volatile("cp.async.wait_group 0;" ::: "memory");

    // ------- block reduction: validated shape, 8 slots (4 zero pads) -------
    float v0 = LO(M1) + HI(M1), v1 = LO(M2) + HI(M2);
    float v2 = LO(M3) + HI(M3), v3 = LO(M4) + HI(M4);
    float v4 = 0.0f, v5 = 0.0f, v6 = 0.0f, v7 = 0.0f;

    const unsigned m = 0xffffffffu;
#pragma unroll
    for (int o = 16; o; o >>= 1) {
        v0 += __shfl_xor_sync(m, v0, o);
        v1 += __shfl_xor_sync(m, v1, o);
        v2 += __shfl_xor_sync(m, v2, o);
        v3 += __shfl_xor_sync(m, v3, o);
    }

    float* sh   = shred;            // [8][8]
    float* s8   = shred + 64;       // [8]
    int*  sLast = (int*)(shred + 72);

    __syncthreads();                // all ring reads/writes done before aliasing
    const int lane = tid & 31;
    const int wp   = tid >> 5;      // 8 warps
    if (lane == 0) {
        sh[0 * 8 + wp] = v0; sh[1 * 8 + wp] = v1;
        sh[2 * 8 + wp] = v2; sh[3 * 8 + wp] = v3;
        sh[4 * 8 + wp] = v4; sh[5 * 8 + wp] = v5;
        sh[6 * 8 + wp] = v6; sh[7 * 8 + wp] = v7;
    }
    __syncthreads();
    if (tid < 64) {                 // 2 FULL warps in shuffles
        const int q  = tid >> 3;
        const int wj = tid & 7;
        float v = sh[q * 8 + wj];
        v += __shfl_down_sync(m, v, 4, 8);
        v += __shfl_down_sync(m, v, 2, 8);
        v += __shfl_down_sync(m, v, 1, 8);
        if (wj == 0) g_part[q][blk] = v;
    }
    __threadfence();
    __syncthreads();
    if (tid == 0) {
        unsigned old = atomicAdd(&g_ctr, 1u);
        *sLast = ((old % NBLK) == (NBLK - 1)) ? 1 : 0;
    }
    __syncthreads();

    // ---------------- last block: final reduce + epilogue ----------------
    if (*sLast) {
        if (tid < 128) {            // 4 FULL warps in shuffles
            const int q = tid >> 4;   // 8 quantities x 16 lanes
            const int l = tid & 15;
            float v = 0.f;
#pragma unroll
            for (int i = l; i < NBLK; i += 16) v += __ldcg(&g_part[q][i]);
#pragma unroll
            for (int o = 8; o; o >>= 1) v += __shfl_down_sync(m, v, o, 16);
            if (l == 0) s8[q] = v;
        }
        __syncthreads();

        if (tid == 0) {
            const float inv = 1.0f / ((float)NW * (float)NSTEPS);
            const float m1 = s8[0] * inv;   // mean xs
            const float m2 = s8[1] * inv;   // mean xs^2
            const float m3 = s8[2] * inv;   // mean xs^3
            const float m4 = s8[3] * inv;   // mean xs^4

            // linear recombination (er = A0+A1 t+A2 t^2, ei = xs*(B0+B1 t))
            const float Ser   = A0f + A1f * m2 + A2f * m4;
            const float Sei   = B0f * m1 + B1f * m3;
            const float Sxs   = m1;
            const float Sx2   = m2;
            const float Sxer  = A0f * m1 + A1f * m3;
            const float Sxei  = B0f * m2 + B1f * m4;
            const float Sx2er = A0f * m2 + A1f * m4;
            const float Sx2ei = B0f * m3;

            if (out_size == 14) {
                const float Sr   = Sxs + th2;
                const float Srer = Sxer + th2 * Ser;
                const float Srei = Sxei + th2 * Sei;
                float2* o2 = (float2*)out;
                o2[0] = make_float2(Ser, Sei);
                o2[1] = make_float2(0.0f, Sr);
                o2[2] = make_float2(Sx2, 0.0f);
                o2[3] = make_float2(gf * Sxs, 0.0f);
                o2[4] = make_float2(Srei, -Srer);
                o2[5] = make_float2(Sx2er, Sx2ei);
                o2[6] = make_float2(gf * Sxer, gf * Sxei);
            } else {
                out[0] = Ser;                  // Es.re
                out[1] = 0.0f;                 // Ds0.re
                out[2] = Sx2;                  // Ds1.re
                out[3] = gf * Sxs;             // Ds2.re
                out[4] = Sxei + th2 * Sei;     // EDs0.re
                out[5] = Sx2er;                // EDs1.re
                out[6] = gf * Sxer;            // EDs2.re
            }
        }
    }
}

extern "C" void kernel_launch(void* const* d_in, const int* in_sizes, int n_in,
                              void* d_out, int out_size)
{
    const float* theta = (const float*)d_in[0];
    const float* r0    = (const float*)d_in[1];
    const float* sdev  = (const float*)d_in[2];
    const float* noise = (const float*)d_in[3];
    const float* unif  = (const float*)d_in[4];

    cudaFuncSetAttribute(vmc_kernel, cudaFuncAttributeMaxDynamicSharedMemorySize,
                         SMEM_BYTES);

    vmc_kernel<<<NBLK, TPB, SMEM_BYTES>>>(theta, r0, sdev, noise, unif,
                                          (float*)d_out, out_size);
}

// round 15
// speedup vs baseline: 1.0697x; 1.0697x over previous
#include <cuda_runtime.h>
#include <math.h>
#include <stdint.h>

// Problem constants (fixed by the reference)
#define NW      65536
#define TPB     128
#define PPB     128                // walker pairs per block (1 packed pair/thread)
#define NBLK    256                // 32768 pairs / 128; divides 2^32
#define TOTALS  512
#define WARM    128
#define NSTEPS  384
#define CH      16                 // steps per chunk
#define HB      8                  // steps per precompute half-block
#define NCH     (TOTALS / CH)      // 32
#define WARM_CH (WARM / CH)        // 8
#define ROWB    ((size_t)NW * 4)   // gmem bytes per step-row
// smem ring (ull units): stage = [N: CH*PPB][U: CH*PPB]
#define UOFF    (CH * PPB)         // 2048 ull
#define STG     (2 * CH * PPB)     // 4096 ull = 32 KB
#define SMEM_BYTES (3 * STG * 8)   // 96 KB  (x2 blocks/SM = 192 KB)

typedef unsigned long long ull;

// 8 slots (4 moments + 4 zero pads) keeps the validated reduction shape
__device__ float        g_part[8][NBLK];
__device__ unsigned int g_ctr = 0;

// ---------- f32x2 packed helpers ----------
__device__ __forceinline__ ull PKF(float a, float b) {
    ull v; asm("mov.b64 %0, {%1, %2};" : "=l"(v)
               : "r"(__float_as_uint(a)), "r"(__float_as_uint(b)));
    return v;
}
__device__ __forceinline__ ull PKU(unsigned a, unsigned b) {
    ull v; asm("mov.b64 %0, {%1, %2};" : "=l"(v) : "r"(a), "r"(b));
    return v;
}
__device__ __forceinline__ float LO(ull v) { return __uint_as_float((unsigned)v); }
__device__ __forceinline__ float HI(ull v) { return __uint_as_float((unsigned)(v >> 32)); }
__device__ __forceinline__ ull FMA2(ull a, ull b, ull c) {
    ull d; asm("fma.rn.f32x2 %0, %1, %2, %3;" : "=l"(d) : "l"(a), "l"(b), "l"(c));
    return d;
}
__device__ __forceinline__ ull MUL2(ull a, ull b) {
    ull d; asm("mul.rn.f32x2 %0, %1, %2;" : "=l"(d) : "l"(a), "l"(b));
    return d;
}
__device__ __forceinline__ ull ADD2(ull a, ull b) {
    ull d; asm("add.rn.f32x2 %0, %1, %2;" : "=l"(d) : "l"(a), "l"(b));
    return d;
}
__device__ __forceinline__ ull SPL(float a) { return PKF(a, a); }

__device__ __forceinline__ void cp16(uint32_t dst, const void* src) {
    asm volatile("cp.async.cg.shared.global [%0], [%1], 16;" :: "r"(dst), "l"(src));
}

__global__ void __launch_bounds__(TPB, 2) vmc_kernel(
    const float* __restrict__ theta,
    const float* __restrict__ r0,
    const float* __restrict__ sdevp,
    const float* __restrict__ noise,
    const float* __restrict__ unif,
    float* __restrict__ out, int out_size)
{
    extern __shared__ ull ring[];
    float* shred = (float*)ring;             // aliased reduction scratch

    const int tid = threadIdx.x;
    const int blk = blockIdx.x;
    const int w   = blk * PPB + tid;         // walker-pair index

    const float th0 = theta[0];
    const float th1 = theta[1];
    const float th2 = theta[2];
    const float sdev = sdevp[0];

    const float kk = __fmul_rn(-2.0f, th1);   // reference rounding (validated)
    const float gf = 2.0f * th1;

    const ull sd2  = SPL(sdev);
    const ull kk2  = SPL(kk);
    const ull mkk2 = SPL(-kk);

    // cheap comparison-grade ln (validated R11-R13): m in [2/3,4/3), f=m-1
    const ull cm1 = SPL(-1.0f);
    const ull cP5 = SPL(-0.16666667f), cP4 = SPL(0.2f);
    const ull cP3 = SPL(-0.25f),       cP2 = SPL(0.33333334f);
    const ull cP1 = SPL(-0.5f),        cP0 = SPL(1.0f);
    const ull cE  = SPL(8.2629582e-8f);      // 2^-23 * ln 2

    // Energy poly coefficients (fp64 fold once); applied only in epilogue
    const double dth0 = (double)th0, dth1 = (double)th1;
    const double dg = 2.0 * dth1, g2d = dg * dg;
    const double dC1 = -2.0 * exp(-dth1) * cos(dth0);
    const double dC2 =  2.0 * exp(-dth1) * sin(dth0);
    const float A0f = (float)dC1;
    const float A1f = (float)(dC1 * g2d / 2.0);
    const float A2f = (float)(dC1 * g2d / 2.0 * g2d / 12.0);
    const float B0f = (float)(dC2 * dg);
    const float B1f = (float)(dC2 * dg * g2d / 6.0);

    // ---- state: one packed pair per thread ----
    const float2 rr = ((const float2*)r0)[w];
    ull xs  = PKF(__fsub_rn(rr.x, th2), __fsub_rn(rr.y, th2));
    ull xs2 = MUL2(xs, xs);
    ull nkx = MUL2(mkk2, xs2);

    // ---- cp.async geometry: block row = 128 pairs = 1024 B = 64 granules ----
    const uint32_t base = (uint32_t)__cvta_generic_to_shared(ring);
    const int c16  = tid & 63;                // granule within row
    const int rsel = tid >> 6;                // 0/1 -> rows rsel + 2k
    const size_t sliceOff = (size_t)blk * 1024 + (size_t)c16 * 16;
    const char* gN = (const char*)noise + sliceOff;
    const char* gU = (const char*)unif  + sliceOff;

    // chunk = 16 rows; each thread: 8 rows x (N,U) granules of 16 B
#define ISSUE_CHUNK(s0, stg) do {                                            \
        const char* _n = gN + (size_t)(s0) * ROWB;                           \
        const char* _u = gU + (size_t)(s0) * ROWB;                           \
        uint32_t _sb = base + (uint32_t)(stg) * (STG * 8);                   \
        _Pragma("unroll")                                                    \
        for (int _k = 0; _k < 8; _k++) {                                     \
            int _row = _k * 2 + rsel;                                        \
            uint32_t _d = (uint32_t)(_row * 1024 + c16 * 16);                \
            cp16(_sb + _d,            _n + (size_t)_row * ROWB);             \
            cp16(_sb + UOFF * 8 + _d, _u + (size_t)_row * ROWB);             \
        }                                                                    \
        asm volatile("cp.async.commit_group;" ::: "memory");                 \
    } while (0)

    // packed cheap natural log (off-chain): 8 fma-pipe ops
#define NLOG(u, lgu) do {                                                    \
        unsigned iu0 = (unsigned)(u);                                        \
        unsigned iu1 = (unsigned)((u) >> 32);                                \
        int e0 = (int)((iu0 - 0x3f2aaaabu) & 0xff800000u);                   \
        int e1 = (int)((iu1 - 0x3f2aaaabu) & 0xff800000u);                   \
        float mm0 = __int_as_float((int)iu0 - e0);                           \
        float mm1 = __int_as_float((int)iu1 - e1);                           \
        ull f_ = ADD2(PKF(mm0, mm1), cm1);                                   \
        ull p_ = FMA2(cP5, f_, cP4);                                         \
        p_ = FMA2(p_, f_, cP3);                                              \
        p_ = FMA2(p_, f_, cP2);                                              \
        p_ = FMA2(p_, f_, cP1);                                              \
        p_ = FMA2(p_, f_, cP0);                                              \
        ull ln_ = MUL2(f_, p_);                                              \
        (lgu) = FMA2(PKF((float)e0, (float)e1), cE, ln_);                    \
    } while (0)

    // short recurrence (validated R13); bit-identical trajectory
#define REC(nn, lg) do {                                                     \
        ull xp  = FMA2(sd2, (nn), xs);                                       \
        ull xp2 = MUL2(xp, xp);                                              \
        ull lr  = FMA2(kk2, xp2, nkx);                                       \
        bool aLo = (LO(lg) < LO(lr));                                        \
        bool aHi = (HI(lg) < HI(lr));                                        \
        unsigned xs_lo = aLo ? (unsigned)xp         : (unsigned)xs;          \
        unsigned xs_hi = aHi ? (unsigned)(xp  >> 32) : (unsigned)(xs  >> 32); \
        xs  = PKU(xs_lo, xs_hi);                                             \
        xs2 = MUL2(xs, xs);                                                  \
        nkx = MUL2(mkk2, xs2);                                               \
    } while (0)

    // moment accumulation fused: M1=Sxs M2=St M3=Sxs3 M4=St2 (4 ops)
#define MEAS() do {                                                          \
        ull t = xs2;                                                         \
        M1 = ADD2(M1, xs);                                                   \
        M2 = ADD2(M2, t);                                                    \
        M3 = FMA2(xs, t, M3);                                                \
        M4 = FMA2(t,  t, M4);                                                \
    } while (0)

    ull M1 = 0, M2 = 0, M3 = 0, M4 = 0;

    // prologue: 2 chunks in flight (3-stage ring)
    ISSUE_CHUNK(0 * CH, 0);
    ISSUE_CHUNK(1 * CH, 1);

    int cur = 0;                    // slot of chunk c
    for (int c = 0; c < NCH; c++) {
        asm volatile("cp.async.wait_group 1;" ::: "memory");  // chunk c complete
        __syncthreads();            // visibility + all threads done with slot iss

        const int iss = (cur == 0) ? 2 : cur - 1;   // (c+2) % 3
        if (c + 2 < NCH) {
            ISSUE_CHUNK((c + 2) * CH, iss);
        } else {
            asm volatile("cp.async.commit_group;" ::: "memory");
        }

        const ull* st = ring + (size_t)cur * STG;
        const bool meas = (c >= WARM_CH);

#pragma unroll
        for (int h = 0; h < CH / HB; h++) {
            ull nn[HB], lg[HB];
#pragma unroll
            for (int j = 0; j < HB; j++) {
                const int row = h * HB + j;
                nn[j] = st[row * PPB + tid];
                ull u = st[UOFF + row * PPB + tid];
                NLOG(u, lg[j]);
            }
            if (!meas) {
#pragma unroll
                for (int j = 0; j < HB; j++) { REC(nn[j], lg[j]); }
            } else {
#pragma unroll
                for (int j = 0; j < HB; j++) { REC(nn[j], lg[j]); MEAS(); }
            }
        }
        cur = (cur == 2) ? 0 : cur + 1;
    }

    // ------- block reduction: 4 warps, 8 slots (4 zero pads) -------
    float v0 = LO(M1) + HI(M1), v1 = LO(M2) + HI(M2);
    float v2 = LO(M3) + HI(M3), v3 = LO(M4) + HI(M4);
    float v4 = 0.0f, v5 = 0.0f, v6 = 0.0f, v7 = 0.0f;

    const unsigned m = 0xffffffffu;
#pragma unroll
    for (int o = 16; o; o >>= 1) {
        v0 += __shfl_xor_sync(m, v0, o);
        v1 += __shfl_xor_sync(m, v1, o);
        v2 += __shfl_xor_sync(m, v2, o);
        v3 += __shfl_xor_sync(m, v3, o);
    }

    float* sh   = shred;            // [8][4]
    float* s8   = shred + 32;       // [8]
    int*  sLast = (int*)(shred + 40);

    __syncthreads();                // ring reads done before aliasing
    const int lane = tid & 31;
    const int wp   = tid >> 5;      // 4 warps
    if (lane == 0) {
        sh[0 * 4 + wp] = v0; sh[1 * 4 + wp] = v1;
        sh[2 * 4 + wp] = v2; sh[3 * 4 + wp] = v3;
        sh[4 * 4 + wp] = v4; sh[5 * 4 + wp] = v5;
        sh[6 * 4 + wp] = v6; sh[7 * 4 + wp] = v7;
    }
    __syncthreads();
    if (tid < 32) {                 // 1 FULL warp in shuffles (R6-validated)
        const int q  = tid >> 2;
        const int wj = tid & 3;
        float v = sh[q * 4 + wj];
        v += __shfl_down_sync(m, v, 2, 4);
        v += __shfl_down_sync(m, v, 1, 4);
        if (wj == 0) g_part[q][blk] = v;
    }
    __threadfence();
    __syncthreads();
    if (tid == 0) {
        unsigned old = atomicAdd(&g_ctr, 1u);
        *sLast = ((old % NBLK) == (NBLK - 1)) ? 1 : 0;
    }
    __syncthreads();

    // ---------------- last block: final reduce + epilogue ----------------
    if (*sLast) {
        {
            const int q = tid >> 4;   // 8 quantities x 16 lanes (tid < 128 = all)
            const int l = tid & 15;
            float v = 0.f;
#pragma unroll
            for (int i = l; i < NBLK; i += 16) v += __ldcg(&g_part[q][i]);
#pragma unroll
            for (int o = 8; o; o >>= 1) v += __shfl_down_sync(m, v, o, 16);
            if (l == 0) s8[q] = v;
        }
        __syncthreads();

        if (tid == 0) {
            const float inv = 1.0f / ((float)NW * (float)NSTEPS);
            const float m1 = s8[0] * inv;   // mean xs
            const float m2 = s8[1] * inv;   // mean xs^2
            const float m3 = s8[2] * inv;   // mean xs^3
            const float m4 = s8[3] * inv;   // mean xs^4

            // linear recombination (er = A0+A1 t+A2 t^2, ei = xs*(B0+B1 t))
            const float Ser   = A0f + A1f * m2 + A2f * m4;
            const float Sei   = B0f * m1 + B1f * m3;
            const float Sxs   = m1;
            const float Sx2   = m2;
            const float Sxer  = A0f * m1 + A1f * m3;
            const float Sxei  = B0f * m2 + B1f * m4;
            const float Sx2er = A0f * m2 + A1f * m4;
            const float Sx2ei = B0f * m3;

            if (out_size == 14) {
                const float Sr   = Sxs + th2;
                const float Srer = Sxer + th2 * Ser;
                const float Srei = Sxei + th2 * Sei;
                float2* o2 = (float2*)out;
                o2[0] = make_float2(Ser, Sei);
                o2[1] = make_float2(0.0f, Sr);
                o2[2] = make_float2(Sx2, 0.0f);
                o2[3] = make_float2(gf * Sxs, 0.0f);
                o2[4] = make_float2(Srei, -Srer);
                o2[5] = make_float2(Sx2er, Sx2ei);
                o2[6] = make_float2(gf * Sxer, gf * Sxei);
            } else {
                out[0] = Ser;                  // Es.re
                out[1] = 0.0f;                 // Ds0.re
                out[2] = Sx2;                  // Ds1.re
                out[3] = gf * Sxs;             // Ds2.re
                out[4] = Sxei + th2 * Sei;     // EDs0.re
                out[5] = Sx2er;                // EDs1.re
                out[6] = gf * Sxer;            // EDs2.re
            }
        }
    }
}

extern "C" void kernel_launch(void* const* d_in, const int* in_sizes, int n_in,
                              void* d_out, int out_size)
{
    const float* theta = (const float*)d_in[0];
    const float* r0    = (const float*)d_in[1];
    const float* sdev  = (const float*)d_in[2];
    const float* noise = (const float*)d_in[3];
    const float* unif  = (const float*)d_in[4];

    cudaFuncSetAttribute(vmc_kernel, cudaFuncAttributeMaxDynamicSharedMemorySize,
                         SMEM_BYTES);

    vmc_kernel<<<NBLK, TPB, SMEM_BYTES>>>(theta, r0, sdev, noise, unif,
                                          (float*)d_out, out_size);
}